// round 5
// baseline (speedup 1.0000x reference)
#include <cuda_runtime.h>
#include <math.h>

#define NN 100000
#define NE 1600000
#define MAXIT 50
#define THREADS 512

typedef unsigned long long u64;

// ---------------- device global scratch ----------------
__device__ __align__(16) float      g_state[2][NN * 8]; // padded 8 floats/node (5 used)
__device__ __align__(16) ulonglong2 g_pre[NE * 4];      // sorted: 15 pre-acts f32 + src bits (64B/edge)
__device__ __align__(8)  int2       g_rv[NE];           // sorted: {row, val_bits}
__device__ int g_hist[NN];
__device__ int g_ptr[NN];
__device__ int g_bsum[256];
__device__ int g_bpre[256];
__device__ unsigned g_barc;
__device__ unsigned g_barg;
__device__ int g_flags[64];

// ---------------- fast math ----------------
__device__ __forceinline__ float fast_tanh(float x) {
    float t;
    asm("ex2.approx.f32 %0, %1;" : "=f"(t) : "f"(x * 2.885390081777927f)); // exp(2x)
    float r;
    asm("rcp.approx.f32 %0, %1;" : "=f"(r) : "f"(t + 1.0f));
    return fmaf(-2.0f, r, 1.0f);
}
__device__ __forceinline__ float fast_exp(float x) {
    float t;
    asm("ex2.approx.f32 %0, %1;" : "=f"(t) : "f"(x * 1.4426950408889634f));
    return t;
}
__device__ __forceinline__ u64 pack2(float lo, float hi) {
    u64 r;
    asm("mov.b64 %0, {%1, %2};" : "=l"(r) : "f"(lo), "f"(hi));
    return r;
}
__device__ __forceinline__ void unpack2(float& lo, float& hi, u64 v) {
    asm("mov.b64 {%0, %1}, %2;" : "=f"(lo), "=f"(hi) : "l"(v));
}
__device__ __forceinline__ u64 fma2(u64 a, u64 b, u64 c) {
    u64 d;
    asm("fma.rn.f32x2 %0, %1, %2, %3;" : "=l"(d) : "l"(a), "l"(b), "l"(c));
    return d;
}

// ---------------- grid barrier (grid = #SMs, 1 block/SM) ----------------
__device__ __forceinline__ void gsync() {
    __syncthreads();
    if (threadIdx.x == 0) {
        __threadfence();
        unsigned gen = *((volatile unsigned*)&g_barg);
        unsigned t = atomicAdd(&g_barc, 1u);
        if (t == gridDim.x - 1) {
            g_barc = 0;
            __threadfence();
            atomicAdd(&g_barg, 1u);
        } else {
            while (*((volatile unsigned*)&g_barg) == gen) { __nanosleep(32); }
        }
        __threadfence();
    }
    __syncthreads();
}

// ---------------- smem weight layout ----------------
#define OW1F 0
#define OB1  128
#define OW1S 144
#define OW2T 224
#define OB2  304
#define OW3  312
#define OB3  392
#define OW4T 408
#define OB4  520
#define SWSZ 528

extern "C" __global__ void __launch_bounds__(THREADS, 1)
gnn_persistent(const float* __restrict__ edge_feat,
               const int*   __restrict__ edge_src,
               const int*   __restrict__ arc_rows,
               const float* __restrict__ arc_vals,
               const float* __restrict__ state_init,
               const float* __restrict__ old_init,
               const float* __restrict__ W1, const float* __restrict__ b1,
               const float* __restrict__ W2, const float* __restrict__ b2,
               const float* __restrict__ W3, const float* __restrict__ b3,
               const float* __restrict__ W4, const float* __restrict__ b4,
               float* __restrict__ out, int out_size)
{
    __shared__ __align__(16) float sw[SWSZ];
    __shared__ int sscan[THREADS];
    const int tid  = threadIdx.x;
    const int lane = tid & 31;
    const int gtid = blockIdx.x * blockDim.x + tid;
    const int gsz  = gridDim.x * blockDim.x;

    // ---- weights -> smem ----
    for (int i = tid; i < SWSZ; i += THREADS) sw[i] = 0.0f;
    __syncthreads();
    for (int i = tid; i < 13 * 15; i += THREADS) {
        int r = i / 15, c = i % 15;
        if (r < 8) sw[OW1F + r * 16 + c] = W1[i];
        else       sw[OW1S + (r - 8) * 16 + c] = W1[i];
    }
    for (int i = tid; i < 15; i += THREADS) sw[OB1 + i] = b1[i];
    for (int i = tid; i < 75; i += THREADS) sw[OW2T + (i % 5) * 16 + (i / 5)] = W2[i];
    for (int i = tid; i < 5;  i += THREADS) sw[OB2 + i] = b2[i];
    for (int i = tid; i < 50; i += THREADS) sw[OW3 + (i / 10) * 16 + (i % 10)] = W3[i];
    for (int i = tid; i < 10; i += THREADS) sw[OB3 + i] = b3[i];
    for (int i = tid; i < 70; i += THREADS) sw[OW4T + (i % 7) * 16 + (i / 7)] = W4[i];
    for (int i = tid; i < 7;  i += THREADS) sw[OB4 + i] = b4[i];
    __syncthreads();

    // ---- init: flags, hist, states ----
    for (int i = gtid; i < 64; i += gsz) g_flags[i] = 0;
    for (int i = gtid; i < NN; i += gsz) g_hist[i] = 0;
    for (int n = gtid; n < NN; n += gsz) {
        float* p0 = &g_state[0][n * 8];
        float* p1 = &g_state[1][n * 8];
        #pragma unroll
        for (int d = 0; d < 5; ++d) {
            p0[d] = state_init[n * 5 + d];
            p1[d] = old_init[n * 5 + d];
        }
        #pragma unroll
        for (int d = 5; d < 8; ++d) { p0[d] = 0.0f; p1[d] = 0.0f; }
    }
    gsync();

    // ---- histogram of destination rows ----
    for (int e = gtid; e < NE; e += gsz) atomicAdd(&g_hist[arc_rows[e]], 1);
    gsync();

    // ---- exclusive prefix scan over 100K bins (2 bins/thread) ----
    {
        int i0 = 2 * gtid, i1 = 2 * gtid + 1;
        int a = (i0 < NN) ? g_hist[i0] : 0;
        int b = (i1 < NN) ? g_hist[i1] : 0;
        int s = a + b;
        sscan[tid] = s;
        __syncthreads();
        for (int d = 1; d < THREADS; d <<= 1) {
            int x = (tid >= d) ? sscan[tid - d] : 0;
            __syncthreads();
            sscan[tid] += x;
            __syncthreads();
        }
        int incl = sscan[tid];
        int excl = incl - s;
        if (tid == THREADS - 1) g_bsum[blockIdx.x] = incl;
        gsync();
        if (blockIdx.x == 0 && tid == 0) {
            int acc = 0;
            for (int k = 0; k < (int)gridDim.x; ++k) { g_bpre[k] = acc; acc += g_bsum[k]; }
        }
        gsync();
        int base = g_bpre[blockIdx.x] + excl;
        if (i0 < NN) g_ptr[i0] = base;
        if (i1 < NN) g_ptr[i1] = base + a;
    }
    gsync();

    // ---- scatter pass: compute pre-acts and write records in row-sorted order ----
    for (int e = gtid; e < NE; e += gsz) {
        const float4* efp = (const float4*)(edge_feat + (size_t)e * 8);
        float4 f0 = efp[0], f1 = efp[1];
        float ef[8] = {f0.x, f0.y, f0.z, f0.w, f1.x, f1.y, f1.z, f1.w};
        float h[16];
        #pragma unroll
        for (int j = 0; j < 16; ++j) h[j] = sw[OB1 + j];
        #pragma unroll
        for (int f = 0; f < 8; ++f) {
            float s = ef[f];
            const float4* w = (const float4*)&sw[OW1F + f * 16];
            #pragma unroll
            for (int q = 0; q < 4; ++q) {
                float4 wq = w[q];
                h[q * 4 + 0] = fmaf(s, wq.x, h[q * 4 + 0]);
                h[q * 4 + 1] = fmaf(s, wq.y, h[q * 4 + 1]);
                h[q * 4 + 2] = fmaf(s, wq.z, h[q * 4 + 2]);
                h[q * 4 + 3] = fmaf(s, wq.w, h[q * 4 + 3]);
            }
        }
        int row = arc_rows[e];
        int src = edge_src[e];
        int pos = atomicAdd(&g_ptr[row], 1);
        ulonglong2* pp = &g_pre[(size_t)pos * 4];
        ulonglong2 t;
        t.x = pack2(h[0],  h[1]);  t.y = pack2(h[2],  h[3]);  pp[0] = t;
        t.x = pack2(h[4],  h[5]);  t.y = pack2(h[6],  h[7]);  pp[1] = t;
        t.x = pack2(h[8],  h[9]);  t.y = pack2(h[10], h[11]); pp[2] = t;
        t.x = pack2(h[12], h[13]); t.y = pack2(h[14], __int_as_float(src)); pp[3] = t;
        g_rv[pos] = make_int2(row, __float_as_int(arc_vals[e]));
    }
    gsync();

    // ---- fixed-point loop ----
    int cur = 0;
    int num = 0;
    for (int it = 0; it < MAXIT; ++it) {
        // node phase: dist + zero old buffer (becomes accumulator)
        const float* sb = g_state[cur];
        float*       ob = g_state[cur ^ 1];
        int flag = 0;
        for (int n = gtid; n < NN; n += gsz) {
            const float4* sp = (const float4*)(sb + n * 8);
            float4*       op = (float4*)(ob + n * 8);
            float4 s0 = sp[0]; float s4 = sb[n * 8 + 4];
            float4 o0 = op[0]; float o4 = ob[n * 8 + 4];
            float d0 = s0.x - o0.x, d1 = s0.y - o0.y, d2 = s0.z - o0.z,
                  d3 = s0.w - o0.w, d4 = s4 - o4;
            float ss = d0*d0 + d1*d1 + d2*d2 + d3*d3 + d4*d4;
            if (sqrtf(ss + 1e-11f) > 0.01f) flag = 1;
            op[0] = make_float4(0.f, 0.f, 0.f, 0.f);
            op[1] = make_float4(0.f, 0.f, 0.f, 0.f);
        }
        int bf = __syncthreads_or(flag);
        if (tid == 0 && bf) atomicOr(&g_flags[it], 1);
        gsync();
        if (*((volatile int*)&g_flags[it]) == 0) break;
        num++;

        // edge phase over sorted edges: full warps, segmented reduction
        const float* __restrict__ sbase = g_state[cur];
        float*       __restrict__ dbase = g_state[cur ^ 1];

        for (int base = 0; base < NE; base += gsz) {
            int e = base + gtid;
            bool v = (e < NE);
            int ec = v ? e : (NE - 1);

            int2 rv = g_rv[ec];
            const ulonglong2* pp = &g_pre[(size_t)ec * 4];
            ulonglong2 q0 = pp[0], q1 = pp[1], q2 = pp[2], q3 = pp[3];

            float h14, srcf;
            unpack2(h14, srcf, q3.y);
            int src = __float_as_int(srcf);
            const float* sp = sbase + (size_t)src * 8;
            float4 sv = *(const float4*)sp;
            float s4 = sp[4];

            u64 h[8] = {q0.x, q0.y, q1.x, q1.y, q2.x, q2.y, q3.x, pack2(h14, 0.0f)};
            float sd[5] = {sv.x, sv.y, sv.z, sv.w, s4};

            // layer 1 (state part)
            #pragma unroll
            for (int d = 0; d < 5; ++d) {
                u64 sa = pack2(sd[d], sd[d]);
                const ulonglong2* wr = (const ulonglong2*)&sw[OW1S + d * 16];
                #pragma unroll
                for (int qq = 0; qq < 4; ++qq) {
                    ulonglong2 w = wr[qq];
                    h[2 * qq]     = fma2(sa, w.x, h[2 * qq]);
                    h[2 * qq + 1] = fma2(sa, w.y, h[2 * qq + 1]);
                }
            }
            #pragma unroll
            for (int k = 0; k < 8; ++k) {
                float lo, hi;
                unpack2(lo, hi, h[k]);
                h[k] = pack2(fast_tanh(lo), fast_tanh(hi));
            }
            // layer 2
            float val = __int_as_float(rv.y);
            float o0v, o1v, o2v, o3v, o4v;
            {
                float oo[5];
                #pragma unroll
                for (int c = 0; c < 5; ++c) {
                    const ulonglong2* wr = (const ulonglong2*)&sw[OW2T + c * 16];
                    u64 a0 = 0ull, a1 = 0ull;
                    #pragma unroll
                    for (int qq = 0; qq < 4; ++qq) {
                        ulonglong2 w = wr[qq];
                        a0 = fma2(h[2 * qq],     w.x, a0);
                        a1 = fma2(h[2 * qq + 1], w.y, a1);
                    }
                    float x0, x1, y0, y1;
                    unpack2(x0, x1, a0); unpack2(y0, y1, a1);
                    float acc = sw[OB2 + c] + ((x0 + x1) + (y0 + y1));
                    oo[c] = fast_tanh(acc) * val;
                }
                o0v = oo[0]; o1v = oo[1]; o2v = oo[2]; o3v = oo[3]; o4v = oo[4];
            }
            if (!v) { o0v = o1v = o2v = o3v = o4v = 0.0f; }

            // segmented inclusive scan by row key within the warp
            int r = v ? rv.x : (0x40000000 + lane);  // unique sentinel: no merge
            #pragma unroll
            for (int d = 1; d < 32; d <<= 1) {
                int   rp = __shfl_up_sync(0xFFFFFFFFu, r,   d);
                float u0 = __shfl_up_sync(0xFFFFFFFFu, o0v, d);
                float u1 = __shfl_up_sync(0xFFFFFFFFu, o1v, d);
                float u2 = __shfl_up_sync(0xFFFFFFFFu, o2v, d);
                float u3 = __shfl_up_sync(0xFFFFFFFFu, o3v, d);
                float u4 = __shfl_up_sync(0xFFFFFFFFu, o4v, d);
                if (lane >= d && rp == r) {
                    o0v += u0; o1v += u1; o2v += u2; o3v += u3; o4v += u4;
                }
            }
            int rn = __shfl_down_sync(0xFFFFFFFFu, r, 1);
            bool tail = (lane == 31) || (rn != r);
            if (tail && v) {
                float* dp = dbase + (size_t)r * 8;
                asm volatile("red.global.add.v4.f32 [%0], {%1, %2, %3, %4};"
                             :: "l"(dp), "f"(o0v), "f"(o1v), "f"(o2v), "f"(o3v) : "memory");
                atomicAdd(dp + 4, o4v);
            }
        }
        gsync();
        cur ^= 1;
    }

    // ---- output head ----
    const float* fs = g_state[cur];
    for (int n = gtid; n < NN; n += gsz) {
        const float* sp = fs + n * 8;
        float s0 = sp[0], s1 = sp[1], s2 = sp[2], s3 = sp[3], s4 = sp[4];
        float o1[10];
        #pragma unroll
        for (int j = 0; j < 10; ++j) {
            float a = sw[OB3 + j];
            a = fmaf(s0, sw[OW3 + 0 * 16 + j], a);
            a = fmaf(s1, sw[OW3 + 1 * 16 + j], a);
            a = fmaf(s2, sw[OW3 + 2 * 16 + j], a);
            a = fmaf(s3, sw[OW3 + 3 * 16 + j], a);
            a = fmaf(s4, sw[OW3 + 4 * 16 + j], a);
            o1[j] = fast_tanh(a);
        }
        float lg[7];
        #pragma unroll
        for (int c = 0; c < 7; ++c) {
            float a = sw[OB4 + c];
            #pragma unroll
            for (int j = 0; j < 10; ++j)
                a = fmaf(o1[j], sw[OW4T + c * 16 + j], a);
            lg[c] = a;
        }
        float m = lg[0];
        #pragma unroll
        for (int c = 1; c < 7; ++c) m = fmaxf(m, lg[c]);
        float ex[7], ssum = 0.0f;
        #pragma unroll
        for (int c = 0; c < 7; ++c) { ex[c] = fast_exp(lg[c] - m); ssum += ex[c]; }
        float inv = 1.0f / ssum;
        #pragma unroll
        for (int c = 0; c < 7; ++c) out[(size_t)n * 7 + c] = ex[c] * inv;
    }
    if (gtid == 0 && out_size > NN * 7) out[NN * 7] = (float)num;
}

extern "C" void kernel_launch(void* const* d_in, const int* in_sizes, int n_in,
                              void* d_out, int out_size) {
    (void)in_sizes; (void)n_in;
    int dev = 0, sms = 148;
    if (cudaGetDevice(&dev) == cudaSuccess)
        cudaDeviceGetAttribute(&sms, cudaDevAttrMultiProcessorCount, dev);

    gnn_persistent<<<sms, THREADS>>>(
        (const float*)d_in[0],
        (const int*)  d_in[1],
        (const int*)  d_in[2],
        (const float*)d_in[3],
        (const float*)d_in[4],
        (const float*)d_in[5],
        (const float*)d_in[6],  (const float*)d_in[7],
        (const float*)d_in[8],  (const float*)d_in[9],
        (const float*)d_in[10], (const float*)d_in[11],
        (const float*)d_in[12], (const float*)d_in[13],
        (float*)d_out, out_size);
}

// round 7
// speedup vs baseline: 1.9805x; 1.9805x over previous
#include <cuda_runtime.h>
#include <math.h>

#define NN 100000
#define NE 1600000
#define MAXIT 50
#define THREADS 512

typedef unsigned long long u64;

// ---------------- device global scratch ----------------
__device__ __align__(16) float      g_state[2][NN * 8]; // padded 8 floats/node (5 used)
__device__ __align__(16) ulonglong2 g_pre[NE * 4];      // sorted: 15 pre-acts f32 + src bits (64B/edge)
__device__ __align__(8)  int2       g_rv[NE];           // sorted: {row, val_bits}
__device__ int g_hist[NN];
__device__ int g_ptr[NN];
__device__ int g_bsum[256];
__device__ int g_bpre[256];
__device__ unsigned g_barc;
__device__ unsigned g_barg;
__device__ int g_flags[64];

// ---------------- fast math ----------------
__device__ __forceinline__ float fast_tanh(float x) {
    float t;
    asm("ex2.approx.f32 %0, %1;" : "=f"(t) : "f"(x * 2.885390081777927f)); // exp(2x)
    float r;
    asm("rcp.approx.f32 %0, %1;" : "=f"(r) : "f"(t + 1.0f));
    return fmaf(-2.0f, r, 1.0f);
}
__device__ __forceinline__ float fast_exp(float x) {
    float t;
    asm("ex2.approx.f32 %0, %1;" : "=f"(t) : "f"(x * 1.4426950408889634f));
    return t;
}
__device__ __forceinline__ u64 pack2(float lo, float hi) {
    u64 r;
    asm("mov.b64 %0, {%1, %2};" : "=l"(r) : "f"(lo), "f"(hi));
    return r;
}
__device__ __forceinline__ void unpack2(float& lo, float& hi, u64 v) {
    asm("mov.b64 {%0, %1}, %2;" : "=f"(lo), "=f"(hi) : "l"(v));
}
__device__ __forceinline__ u64 fma2(u64 a, u64 b, u64 c) {
    u64 d;
    asm("fma.rn.f32x2 %0, %1, %2, %3;" : "=l"(d) : "l"(a), "l"(b), "l"(c));
    return d;
}

// ---------------- grid barrier (grid = #SMs, 1 block/SM) ----------------
__device__ __forceinline__ void gsync() {
    __syncthreads();
    if (threadIdx.x == 0) {
        __threadfence();
        unsigned gen = *((volatile unsigned*)&g_barg);
        unsigned t = atomicAdd(&g_barc, 1u);
        if (t == gridDim.x - 1) {
            g_barc = 0;
            __threadfence();
            atomicAdd(&g_barg, 1u);
        } else {
            while (*((volatile unsigned*)&g_barg) == gen) { __nanosleep(32); }
        }
        __threadfence();
    }
    __syncthreads();
}

// ---------------- smem weight layout ----------------
#define OW1F 0
#define OB1  128
#define OW1S 144
#define OW2T 224
#define OB2  304
#define OW3  312
#define OB3  392
#define OW4T 408
#define OB4  520
#define SWSZ 528

extern "C" __global__ void __launch_bounds__(THREADS, 1)
gnn_persistent(const float* __restrict__ edge_feat,
               const int*   __restrict__ edge_src,
               const int*   __restrict__ arc_rows,
               const float* __restrict__ arc_vals,
               const float* __restrict__ state_init,
               const float* __restrict__ old_init,
               const float* __restrict__ W1, const float* __restrict__ b1,
               const float* __restrict__ W2, const float* __restrict__ b2,
               const float* __restrict__ W3, const float* __restrict__ b3,
               const float* __restrict__ W4, const float* __restrict__ b4,
               float* __restrict__ out, int out_size)
{
    __shared__ __align__(16) float sw[SWSZ];
    __shared__ int sscan[THREADS];
    const int tid  = threadIdx.x;
    const int gtid = blockIdx.x * blockDim.x + tid;
    const int gsz  = gridDim.x * blockDim.x;

    // ---- weights -> smem ----
    for (int i = tid; i < SWSZ; i += THREADS) sw[i] = 0.0f;
    __syncthreads();
    for (int i = tid; i < 13 * 15; i += THREADS) {
        int r = i / 15, c = i % 15;
        if (r < 8) sw[OW1F + r * 16 + c] = W1[i];
        else       sw[OW1S + (r - 8) * 16 + c] = W1[i];
    }
    for (int i = tid; i < 15; i += THREADS) sw[OB1 + i] = b1[i];
    for (int i = tid; i < 75; i += THREADS) sw[OW2T + (i % 5) * 16 + (i / 5)] = W2[i];
    for (int i = tid; i < 5;  i += THREADS) sw[OB2 + i] = b2[i];
    for (int i = tid; i < 50; i += THREADS) sw[OW3 + (i / 10) * 16 + (i % 10)] = W3[i];
    for (int i = tid; i < 10; i += THREADS) sw[OB3 + i] = b3[i];
    for (int i = tid; i < 70; i += THREADS) sw[OW4T + (i % 7) * 16 + (i / 7)] = W4[i];
    for (int i = tid; i < 7;  i += THREADS) sw[OB4 + i] = b4[i];
    __syncthreads();

    // ---- init: flags, hist, states ----
    for (int i = gtid; i < 64; i += gsz) g_flags[i] = 0;
    for (int i = gtid; i < NN; i += gsz) g_hist[i] = 0;
    for (int n = gtid; n < NN; n += gsz) {
        float* p0 = &g_state[0][n * 8];
        float* p1 = &g_state[1][n * 8];
        #pragma unroll
        for (int d = 0; d < 5; ++d) {
            p0[d] = state_init[n * 5 + d];
            p1[d] = old_init[n * 5 + d];
        }
        #pragma unroll
        for (int d = 5; d < 8; ++d) { p0[d] = 0.0f; p1[d] = 0.0f; }
    }
    gsync();

    // ---- histogram of destination rows ----
    for (int e = gtid; e < NE; e += gsz) atomicAdd(&g_hist[arc_rows[e]], 1);
    gsync();

    // ---- exclusive prefix scan over 100K bins (2 bins/thread) ----
    {
        int i0 = 2 * gtid, i1 = 2 * gtid + 1;
        int a = (i0 < NN) ? g_hist[i0] : 0;
        int b = (i1 < NN) ? g_hist[i1] : 0;
        int s = a + b;
        sscan[tid] = s;
        __syncthreads();
        for (int d = 1; d < THREADS; d <<= 1) {
            int x = (tid >= d) ? sscan[tid - d] : 0;
            __syncthreads();
            sscan[tid] += x;
            __syncthreads();
        }
        int incl = sscan[tid];
        int excl = incl - s;
        if (tid == THREADS - 1) g_bsum[blockIdx.x] = incl;
        gsync();
        if (blockIdx.x == 0 && tid == 0) {
            int acc = 0;
            for (int k = 0; k < (int)gridDim.x; ++k) { g_bpre[k] = acc; acc += g_bsum[k]; }
        }
        gsync();
        int base = g_bpre[blockIdx.x] + excl;
        if (i0 < NN) g_ptr[i0] = base;
        if (i1 < NN) g_ptr[i1] = base + a;
    }
    gsync();

    // ---- scatter pass: compute pre-acts and write records in row-sorted order ----
    for (int e = gtid; e < NE; e += gsz) {
        const float4* efp = (const float4*)(edge_feat + (size_t)e * 8);
        float4 f0 = efp[0], f1 = efp[1];
        float ef[8] = {f0.x, f0.y, f0.z, f0.w, f1.x, f1.y, f1.z, f1.w};
        float h[16];
        #pragma unroll
        for (int j = 0; j < 16; ++j) h[j] = sw[OB1 + j];
        #pragma unroll
        for (int f = 0; f < 8; ++f) {
            float s = ef[f];
            const float4* w = (const float4*)&sw[OW1F + f * 16];
            #pragma unroll
            for (int q = 0; q < 4; ++q) {
                float4 wq = w[q];
                h[q * 4 + 0] = fmaf(s, wq.x, h[q * 4 + 0]);
                h[q * 4 + 1] = fmaf(s, wq.y, h[q * 4 + 1]);
                h[q * 4 + 2] = fmaf(s, wq.z, h[q * 4 + 2]);
                h[q * 4 + 3] = fmaf(s, wq.w, h[q * 4 + 3]);
            }
        }
        int row = arc_rows[e];
        int src = edge_src[e];
        int pos = atomicAdd(&g_ptr[row], 1);
        ulonglong2* pp = &g_pre[(size_t)pos * 4];
        ulonglong2 t;
        t.x = pack2(h[0],  h[1]);  t.y = pack2(h[2],  h[3]);  pp[0] = t;
        t.x = pack2(h[4],  h[5]);  t.y = pack2(h[6],  h[7]);  pp[1] = t;
        t.x = pack2(h[8],  h[9]);  t.y = pack2(h[10], h[11]); pp[2] = t;
        t.x = pack2(h[12], h[13]); t.y = pack2(h[14], __int_as_float(src)); pp[3] = t;
        g_rv[pos] = make_int2(row, __float_as_int(arc_vals[e]));
    }
    gsync();

    // ---- fixed-point loop ----
    int cur = 0;
    int num = 0;
    for (int it = 0; it < MAXIT; ++it) {
        // node phase: dist + zero old buffer (becomes accumulator)
        const float* sb = g_state[cur];
        float*       ob = g_state[cur ^ 1];
        int flag = 0;
        for (int n = gtid; n < NN; n += gsz) {
            const float4* sp = (const float4*)(sb + n * 8);
            float4*       op = (float4*)(ob + n * 8);
            float4 s0 = sp[0]; float s4 = sb[n * 8 + 4];
            float4 o0 = op[0]; float o4 = ob[n * 8 + 4];
            float d0 = s0.x - o0.x, d1 = s0.y - o0.y, d2 = s0.z - o0.z,
                  d3 = s0.w - o0.w, d4 = s4 - o4;
            float ss = d0*d0 + d1*d1 + d2*d2 + d3*d3 + d4*d4;
            if (sqrtf(ss + 1e-11f) > 0.01f) flag = 1;
            op[0] = make_float4(0.f, 0.f, 0.f, 0.f);
            op[1] = make_float4(0.f, 0.f, 0.f, 0.f);
        }
        int bf = __syncthreads_or(flag);
        if (tid == 0 && bf) atomicOr(&g_flags[it], 1);
        gsync();
        if (*((volatile int*)&g_flags[it]) == 0) break;
        num++;

        // edge phase over sorted edges: plain per-edge reduction (coalesced by sort),
        // depth-1 software pipeline to cover rec->src->gather latency
        const float* __restrict__ sbase = g_state[cur];
        float*       __restrict__ dbase = g_state[cur ^ 1];

        int e = gtid;
        int2 rvC; ulonglong2 c0, c1, c2, c3; float4 svC; float s4C; float h14C; int srcC;
        if (e < NE) {
            rvC = g_rv[e];
            const ulonglong2* pp = &g_pre[(size_t)e * 4];
            c0 = pp[0]; c1 = pp[1]; c2 = pp[2]; c3 = pp[3];
            float srcf; unpack2(h14C, srcf, c3.y);
            srcC = __float_as_int(srcf);
            const float* sp = sbase + (size_t)srcC * 8;
            svC = *(const float4*)sp;
            s4C = sp[4];
        }
        for (; e < NE; ) {
            const int en = e + gsz;
            // prefetch next
            int2 rvN; ulonglong2 n0, n1, n2, n3; float4 svN; float s4N; float h14N;
            if (en < NE) {
                rvN = g_rv[en];
                const ulonglong2* pp = &g_pre[(size_t)en * 4];
                n0 = pp[0]; n1 = pp[1]; n2 = pp[2]; n3 = pp[3];
                float srcf; unpack2(h14N, srcf, n3.y);
                int srcN = __float_as_int(srcf);
                const float* sp = sbase + (size_t)srcN * 8;
                svN = *(const float4*)sp;
                s4N = sp[4];
            }

            // compute current
            u64 h[8] = {c0.x, c0.y, c1.x, c1.y, c2.x, c2.y, c3.x, pack2(h14C, 0.0f)};
            float sd[5] = {svC.x, svC.y, svC.z, svC.w, s4C};
            #pragma unroll
            for (int d = 0; d < 5; ++d) {
                u64 sa = pack2(sd[d], sd[d]);
                const ulonglong2* wr = (const ulonglong2*)&sw[OW1S + d * 16];
                #pragma unroll
                for (int qq = 0; qq < 4; ++qq) {
                    ulonglong2 w = wr[qq];
                    h[2 * qq]     = fma2(sa, w.x, h[2 * qq]);
                    h[2 * qq + 1] = fma2(sa, w.y, h[2 * qq + 1]);
                }
            }
            #pragma unroll
            for (int k = 0; k < 8; ++k) {
                float lo, hi;
                unpack2(lo, hi, h[k]);
                h[k] = pack2(fast_tanh(lo), fast_tanh(hi));
            }
            float val = __int_as_float(rvC.y);
            float oo[5];
            #pragma unroll
            for (int c = 0; c < 5; ++c) {
                const ulonglong2* wr = (const ulonglong2*)&sw[OW2T + c * 16];
                u64 a0 = 0ull, a1 = 0ull;
                #pragma unroll
                for (int qq = 0; qq < 4; ++qq) {
                    ulonglong2 w = wr[qq];
                    a0 = fma2(h[2 * qq],     w.x, a0);
                    a1 = fma2(h[2 * qq + 1], w.y, a1);
                }
                float x0, x1, y0, y1;
                unpack2(x0, x1, a0); unpack2(y0, y1, a1);
                float acc = sw[OB2 + c] + ((x0 + x1) + (y0 + y1));
                oo[c] = fast_tanh(acc) * val;
            }
            float* dp = dbase + (size_t)rvC.x * 8;
            asm volatile("red.global.add.v4.f32 [%0], {%1, %2, %3, %4};"
                         :: "l"(dp), "f"(oo[0]), "f"(oo[1]), "f"(oo[2]), "f"(oo[3]) : "memory");
            atomicAdd(dp + 4, oo[4]);

            // rotate pipeline
            rvC = rvN; c0 = n0; c1 = n1; c2 = n2; c3 = n3;
            svC = svN; s4C = s4N; h14C = h14N;
            e = en;
        }
        gsync();
        cur ^= 1;
    }

    // ---- output head ----
    const float* fs = g_state[cur];
    for (int n = gtid; n < NN; n += gsz) {
        const float* sp = fs + n * 8;
        float s0 = sp[0], s1 = sp[1], s2 = sp[2], s3 = sp[3], s4 = sp[4];
        float o1[10];
        #pragma unroll
        for (int j = 0; j < 10; ++j) {
            float a = sw[OB3 + j];
            a = fmaf(s0, sw[OW3 + 0 * 16 + j], a);
            a = fmaf(s1, sw[OW3 + 1 * 16 + j], a);
            a = fmaf(s2, sw[OW3 + 2 * 16 + j], a);
            a = fmaf(s3, sw[OW3 + 3 * 16 + j], a);
            a = fmaf(s4, sw[OW3 + 4 * 16 + j], a);
            o1[j] = fast_tanh(a);
        }
        float lg[7];
        #pragma unroll
        for (int c = 0; c < 7; ++c) {
            float a = sw[OB4 + c];
            #pragma unroll
            for (int j = 0; j < 10; ++j)
                a = fmaf(o1[j], sw[OW4T + c * 16 + j], a);
            lg[c] = a;
        }
        float m = lg[0];
        #pragma unroll
        for (int c = 1; c < 7; ++c) m = fmaxf(m, lg[c]);
        float ex[7], ssum = 0.0f;
        #pragma unroll
        for (int c = 0; c < 7; ++c) { ex[c] = fast_exp(lg[c] - m); ssum += ex[c]; }
        float inv = 1.0f / ssum;
        #pragma unroll
        for (int c = 0; c < 7; ++c) out[(size_t)n * 7 + c] = ex[c] * inv;
    }
    if (gtid == 0 && out_size > NN * 7) out[NN * 7] = (float)num;
}

extern "C" void kernel_launch(void* const* d_in, const int* in_sizes, int n_in,
                              void* d_out, int out_size) {
    (void)in_sizes; (void)n_in;
    int dev = 0, sms = 148;
    if (cudaGetDevice(&dev) == cudaSuccess)
        cudaDeviceGetAttribute(&sms, cudaDevAttrMultiProcessorCount, dev);

    gnn_persistent<<<sms, THREADS>>>(
        (const float*)d_in[0],
        (const int*)  d_in[1],
        (const int*)  d_in[2],
        (const float*)d_in[3],
        (const float*)d_in[4],
        (const float*)d_in[5],
        (const float*)d_in[6],  (const float*)d_in[7],
        (const float*)d_in[8],  (const float*)d_in[9],
        (const float*)d_in[10], (const float*)d_in[11],
        (const float*)d_in[12], (const float*)d_in[13],
        (float*)d_out, out_size);
}